// round 5
// baseline (speedup 1.0000x reference)
#include <cuda_runtime.h>

#define N    4096
#define K    10          // fused Jacobi steps per pass
#define BX   256         // tile width
#define BY   128         // tile height
#define VX   232         // valid output width  (halo 12 each side, >= K)
#define VY   108         // valid output height (halo 10 each side)
#define HX   12
#define HY   10
#define TXN  18          // ceil(4096/232)
#define TYN  38          // ceil(4096/108)
#define NTH  1024
#define NW   32
#define R    4           // rows per warp

typedef unsigned long long ull;

// Scratch ping-pong buffer (allocation-free rule: __device__ global).
__device__ float g_buf[(size_t)N * N];

union F2 { ull u; float2 f; };

__device__ __forceinline__ ull addp(ull a, ull b) {
    ull r; asm("add.rn.f32x2 %0,%1,%2;" : "=l"(r) : "l"(a), "l"(b)); return r;
}
__device__ __forceinline__ ull mulp(ull a, ull b) {
    ull r; asm("mul.rn.f32x2 %0,%1,%2;" : "=l"(r) : "l"(a), "l"(b)); return r;
}
__device__ __forceinline__ ull packp(float lo, float hi) {
    F2 t; t.f.x = lo; t.f.y = hi; return t.u;
}
__device__ __forceinline__ float lof(ull a) { F2 t; t.u = a; return t.f.x; }
__device__ __forceinline__ float hif(ull a) { F2 t; t.u = a; return t.f.y; }

__global__ void init_kernel(const float* __restrict__ X,
                            const float* __restrict__ Y,
                            float* __restrict__ out) {
    int i = blockIdx.x * blockDim.x + threadIdx.x;
    float dx = X[i] - 0.5f;
    float dy = Y[i] - 0.5f;
    out[i] = __expf(-50.0f * (dx * dx + dy * dy));
}

// exchange layout (ull units): [parity][top=0/bot=1][warp][BX/2]
#define EXROW (BX / 2)                 // 128 ull per published row
#define EXPAR (2 * NW * EXROW)         // ull per parity

template<bool EDGE>
__device__ __forceinline__ void run_steps(ull (&u)[R][4], ull* exu,
                                          int warp, int lane,
                                          int gx0, int gy0, int ybase) {
    ull mx[4];
    if (EDGE) {
        #pragma unroll
        for (int q = 0; q < 4; q++) {
            int g = gx0 + lane * 8 + 2 * q;
            float a = (g     >= 1 && g     <= N - 2) ? 1.f : 0.f;
            float b = (g + 1 >= 1 && g + 1 <= N - 2) ? 1.f : 0.f;
            mx[q] = packp(a, b);
        }
    }
    const int lrow = lane * 4;   // ull offset within a published row

    #pragma unroll 2
    for (int s = 0; s < K; s++) {
        ull* exP = exu + (s & 1) * EXPAR;
        // publish own (old) top & bottom rows
        *(ulonglong2*)&exP[(0 * NW + warp) * EXROW + lrow]     = make_ulonglong2(u[0][0], u[0][1]);
        *(ulonglong2*)&exP[(0 * NW + warp) * EXROW + lrow + 2] = make_ulonglong2(u[0][2], u[0][3]);
        *(ulonglong2*)&exP[(1 * NW + warp) * EXROW + lrow]     = make_ulonglong2(u[R-1][0], u[R-1][1]);
        *(ulonglong2*)&exP[(1 * NW + warp) * EXROW + lrow + 2] = make_ulonglong2(u[R-1][2], u[R-1][3]);
        __syncthreads();

        ull A0 = 0, A1 = 0, A2 = 0, A3 = 0;
        if (warp > 0) {
            ulonglong2 t0 = *(ulonglong2*)&exP[(1 * NW + warp - 1) * EXROW + lrow];
            ulonglong2 t1 = *(ulonglong2*)&exP[(1 * NW + warp - 1) * EXROW + lrow + 2];
            A0 = t0.x; A1 = t0.y; A2 = t1.x; A3 = t1.y;
        }

        #pragma unroll
        for (int r = 0; r < R; r++) {
            ull D0, D1, D2, D3;
            if (r < R - 1) {
                D0 = u[r+1][0]; D1 = u[r+1][1]; D2 = u[r+1][2]; D3 = u[r+1][3];
            } else {
                D0 = D1 = D2 = D3 = 0;
                if (warp < NW - 1) {
                    ulonglong2 t0 = *(ulonglong2*)&exP[(0 * NW + warp + 1) * EXROW + lrow];
                    ulonglong2 t1 = *(ulonglong2*)&exP[(0 * NW + warp + 1) * EXROW + lrow + 2];
                    D0 = t0.x; D1 = t0.y; D2 = t1.x; D3 = t1.y;
                }
            }
            float c0 = lof(u[r][0]);
            float c7 = hif(u[r][3]);
            float lf = __shfl_up_sync(0xffffffffu, c7, 1);   // lane0: own val -> halo junk, contained
            float rt = __shfl_down_sync(0xffffffffu, c0, 1);

            ull M0 = packp(lf, c0);
            ull M1 = packp(hif(u[r][0]), lof(u[r][1]));
            ull M2 = packp(hif(u[r][1]), lof(u[r][2]));
            ull M3 = packp(hif(u[r][2]), lof(u[r][3]));
            ull M4 = packp(c7, rt);

            // nv = (left+right) + (up+down)  -- NO 0.25: deferred to epilogue
            ull n0 = addp(addp(M0, M1), addp(A0, D0));
            ull n1 = addp(addp(M1, M2), addp(A1, D1));
            ull n2 = addp(addp(M2, M3), addp(A2, D2));
            ull n3 = addp(addp(M3, M4), addp(A3, D3));

            if (EDGE) {
                int gy = gy0 + ybase + r;
                float my = (gy >= 1 && gy <= N - 2) ? 1.f : 0.f;
                ull myp = packp(my, my);
                n0 = mulp(mulp(n0, mx[0]), myp);
                n1 = mulp(mulp(n1, mx[1]), myp);
                n2 = mulp(mulp(n2, mx[2]), myp);
                n3 = mulp(mulp(n3, mx[3]), myp);
            }
            A0 = u[r][0]; A1 = u[r][1]; A2 = u[r][2]; A3 = u[r][3];
            u[r][0] = n0; u[r][1] = n1; u[r][2] = n2; u[r][3] = n3;
        }
    }
}

__global__ __launch_bounds__(NTH, 1)
void jacobi_pass(const float* __restrict__ in, float* __restrict__ out) {
    extern __shared__ ull exu[];   // 2 parities * 2 rows * 32 warps * 128 ull = 128 KB

    const int tid   = threadIdx.x;
    const int lane  = tid & 31;
    const int warp  = tid >> 5;
    const int x8    = lane * 8;
    const int gx0   = blockIdx.x * VX - HX;   // ≡ 0 mod 4 -> 16B-aligned accesses
    const int gy0   = blockIdx.y * VY - HY;
    const int ybase = warp * R;

    const bool interior =
        (gx0 >= 1) && (gx0 + BX - 1 <= N - 2) &&
        (gy0 >= 1) && (gy0 + BY - 1 <= N - 2);

    ull u[R][4];

    // ---- load 4 rows x 8 cols into registers ----
    if (interior) {
        #pragma unroll
        for (int r = 0; r < R; r++) {
            const ulonglong2* p =
                (const ulonglong2*)(in + (size_t)(gy0 + ybase + r) * N + gx0 + x8);
            ulonglong2 a = p[0], b = p[1];
            u[r][0] = a.x; u[r][1] = a.y; u[r][2] = b.x; u[r][3] = b.y;
        }
    } else {
        #pragma unroll
        for (int r = 0; r < R; r++) {
            int gy = gy0 + ybase + r;
            #pragma unroll
            for (int q = 0; q < 4; q++) {
                float a = 0.f, b = 0.f;
                int g = gx0 + x8 + 2 * q;
                if (gy >= 0 && gy < N) {
                    const float* row = in + (size_t)gy * N;
                    if (g     >= 0 && g     < N) a = row[g];
                    if (g + 1 >= 0 && g + 1 < N) b = row[g + 1];
                }
                u[r][q] = packp(a, b);
            }
        }
    }
    __syncthreads();

    if (interior)
        run_steps<false>(u, exu, warp, lane, gx0, gy0, ybase);
    else
        run_steps<true>(u, exu, warp, lane, gx0, gy0, ybase);

    // ---- epilogue: scale by 0.25^K = 2^-20 (exact) and store valid center ----
    const ull scp = packp(0x1p-20f, 0x1p-20f);
    #pragma unroll
    for (int r = 0; r < R; r++) {
        int ty = ybase + r;
        if (ty < HY || ty > BY - 1 - HY) continue;     // valid rows [10,117]
        int gy = gy0 + ty;
        if (gy >= N) continue;
        float* rowp = out + (size_t)gy * N;
        #pragma unroll
        for (int h = 0; h < 2; h++) {
            int c0 = x8 + 4 * h;                        // tile col of this float4
            if (c0 < HX || c0 + 3 > HX + VX - 1) continue;  // valid cols [12,243]
            int gx = gx0 + c0;
            ull a = mulp(u[r][2 * h],     scp);
            ull b = mulp(u[r][2 * h + 1], scp);
            if (gx + 3 < N) {
                *(float4*)&rowp[gx] =
                    make_float4(lof(a), hif(a), lof(b), hif(b));
            } else {
                float v[4] = { lof(a), hif(a), lof(b), hif(b) };
                #pragma unroll
                for (int e = 0; e < 4; e++)
                    if (gx + e < N) rowp[gx + e] = v[e];
            }
        }
    }
}

extern "C" void kernel_launch(void* const* d_in, const int* in_sizes, int n_in,
                              void* d_out, int out_size) {
    const float* X = (const float*)d_in[0];
    const float* Y = (const float*)d_in[1];
    float* A = (float*)d_out;
    float* B;
    cudaGetSymbolAddress((void**)&B, g_buf);

    const int smem_bytes = 2 * EXPAR * (int)sizeof(ull);   // 131072
    cudaFuncSetAttribute(jacobi_pass,
                         cudaFuncAttributeMaxDynamicSharedMemorySize, smem_bytes);

    // init: x0 -> A
    init_kernel<<<(N * N) / 256, 256>>>(X, Y, A);

    // 10 passes of K=10 fused steps each; 10 even -> final lands in A (=d_out)
    dim3 grid(TXN, TYN);
    for (int p = 0; p < 100 / K; p++) {
        const float* src = (p % 2 == 0) ? A : B;
        float*       dst = (p % 2 == 0) ? B : A;
        jacobi_pass<<<grid, NTH, smem_bytes>>>(src, dst);
    }
}

// round 6
// speedup vs baseline: 1.4343x; 1.4343x over previous
#include <cuda_runtime.h>

#define N    4096
#define K    10          // fused Jacobi steps per pass
#define TX   108         // output tile edge (TX + 2K = 128)
#define BW   128         // tile edge
#define NBLK 38          // ceil(4096 / 108)
#define NTH  512
#define NW   16          // warps per CTA
#define R    8           // rows per warp (NW * R == BW)

// Scratch ping-pong buffer (allocation-free rule: __device__ global).
__device__ float g_buf[(size_t)N * N];

// Exchange buffer type: [step parity][top=0/bot=1][warp][col]
typedef float ExBuf[2][NW][BW];

template<bool EDGE>
__device__ __forceinline__ void run_steps(float4 (&u)[R], ExBuf* ex,
                                          int warp, int x4,
                                          int gx0, int gy0, int ybase) {
    float mx0 = 1.f, mx1 = 1.f, mx2 = 1.f, mx3 = 1.f;
    if (EDGE) {
        int g = gx0 + x4;
        mx0 = (g + 0 >= 1 && g + 0 <= N - 2) ? 1.f : 0.f;
        mx1 = (g + 1 >= 1 && g + 1 <= N - 2) ? 1.f : 0.f;
        mx2 = (g + 2 >= 1 && g + 2 <= N - 2) ? 1.f : 0.f;
        mx3 = (g + 3 >= 1 && g + 3 <= N - 2) ? 1.f : 0.f;
    }

    #pragma unroll 2
    for (int s = 0; s < K; s++) {
        const int par = s & 1;

        // publish own boundary rows (old values) for neighbor warps
        *(float4*)&ex[par][0][warp][x4] = u[0];       // my top row
        *(float4*)&ex[par][1][warp][x4] = u[R - 1];   // my bottom row
        __syncthreads();

        float4 above = make_float4(0.f, 0.f, 0.f, 0.f);
        if (warp > 0)
            above = *(const float4*)&ex[par][1][warp - 1][x4];
        float4 bedge = make_float4(0.f, 0.f, 0.f, 0.f);
        if (warp < NW - 1)
            bedge = *(const float4*)&ex[par][0][warp + 1][x4];

        #pragma unroll
        for (int r = 0; r < R; r++) {
            float4 cur = u[r];
            float4 dn  = (r < R - 1) ? u[r + 1] : bedge;
            float lf = __shfl_up_sync(0xffffffffu, cur.w, 1);
            float rt = __shfl_down_sync(0xffffffffu, cur.x, 1);

            float4 nv;
            nv.x = __fmaf_rn(lf,    0.25f, __fmaf_rn(cur.y, 0.25f,
                   __fmaf_rn(above.x, 0.25f, dn.x * 0.25f)));
            nv.y = __fmaf_rn(cur.x, 0.25f, __fmaf_rn(cur.z, 0.25f,
                   __fmaf_rn(above.y, 0.25f, dn.y * 0.25f)));
            nv.z = __fmaf_rn(cur.y, 0.25f, __fmaf_rn(cur.w, 0.25f,
                   __fmaf_rn(above.z, 0.25f, dn.z * 0.25f)));
            nv.w = __fmaf_rn(cur.z, 0.25f, __fmaf_rn(rt,    0.25f,
                   __fmaf_rn(above.w, 0.25f, dn.w * 0.25f)));

            if (EDGE) {
                int gy = gy0 + ybase + r;
                float my = (gy >= 1 && gy <= N - 2) ? 1.f : 0.f;
                nv.x *= my * mx0; nv.y *= my * mx1;
                nv.z *= my * mx2; nv.w *= my * mx3;
            }

            u[r]  = nv;
            above = cur;   // old value of this row feeds the next row
        }
    }
}

__device__ __forceinline__ void store_center(float4 (&u)[R], float* __restrict__ out,
                                             int warp, int lane, int x4,
                                             int gx0, int gy0, int ybase) {
    #pragma unroll
    for (int r = 0; r < R; r++) {
        int ty = ybase + r;
        if (ty < K || ty > BW - 1 - K) continue;
        int gy = gy0 + ty;
        if (gy >= N) continue;               // gy >= 0 guaranteed (ty >= K)
        float* row = out + (size_t)gy * N;
        int g = gx0 + x4;
        if (x4 + 0 >= K && x4 + 0 <= BW - 1 - K && g + 0 < N) row[g + 0] = u[r].x;
        if (x4 + 1 >= K && x4 + 1 <= BW - 1 - K && g + 1 < N) row[g + 1] = u[r].y;
        if (x4 + 2 >= K && x4 + 2 <= BW - 1 - K && g + 2 < N) row[g + 2] = u[r].z;
        if (x4 + 3 >= K && x4 + 3 <= BW - 1 - K && g + 3 < N) row[g + 3] = u[r].w;
    }
}

// ---- pass 0: compute x0 = exp(-50((X-.5)^2+(Y-.5)^2)) in-register, then K steps ----
__global__ __launch_bounds__(NTH, 2)
void jacobi_first(const float* __restrict__ X, const float* __restrict__ Y,
                  float* __restrict__ out) {
    __shared__ ExBuf ex[2];

    const int tid   = threadIdx.x;
    const int lane  = tid & 31;
    const int warp  = tid >> 5;
    const int x4    = lane * 4;
    const int gx0   = blockIdx.x * TX - K;
    const int gy0   = blockIdx.y * TX - K;
    const int ybase = warp * R;

    const bool tile_interior =
        (gx0 >= 1) && (gx0 + BW - 1 <= N - 2) &&
        (gy0 >= 1) && (gy0 + BW - 1 <= N - 2);

    float4 u[R];

    if (tile_interior) {
        #pragma unroll
        for (int r = 0; r < R; r++) {
            size_t base = (size_t)(gy0 + ybase + r) * N + gx0 + x4;
            #pragma unroll
            for (int e = 0; e < 4; e++) {
                float dx = X[base + e] - 0.5f;
                float dy = Y[base + e] - 0.5f;
                (&u[r].x)[e] = __expf(-50.0f * (dx * dx + dy * dy));
            }
        }
    } else {
        #pragma unroll
        for (int r = 0; r < R; r++) {
            int gy = gy0 + ybase + r;
            float4 v = make_float4(0.f, 0.f, 0.f, 0.f);
            if (gy >= 0 && gy < N) {
                size_t base = (size_t)gy * N;
                int g = gx0 + x4;
                #pragma unroll
                for (int e = 0; e < 4; e++) {
                    if (g + e >= 0 && g + e < N) {
                        float dx = X[base + g + e] - 0.5f;
                        float dy = Y[base + g + e] - 0.5f;
                        (&v.x)[e] = __expf(-50.0f * (dx * dx + dy * dy));
                    }
                }
            }
            u[r] = v;
        }
    }

    if (tile_interior)
        run_steps<false>(u, ex, warp, x4, gx0, gy0, ybase);
    else
        run_steps<true>(u, ex, warp, x4, gx0, gy0, ybase);

    store_center(u, out, warp, lane, x4, gx0, gy0, ybase);
}

// ---- passes 1..9: load prev state, K steps ----
__global__ __launch_bounds__(NTH, 2)
void jacobi_pass(const float* __restrict__ in, float* __restrict__ out) {
    __shared__ ExBuf ex[2];

    const int tid   = threadIdx.x;
    const int lane  = tid & 31;
    const int warp  = tid >> 5;
    const int x4    = lane * 4;
    const int gx0   = blockIdx.x * TX - K;
    const int gy0   = blockIdx.y * TX - K;
    const int ybase = warp * R;

    const bool tile_interior =
        (gx0 >= 1) && (gx0 + BW - 1 <= N - 2) &&
        (gy0 >= 1) && (gy0 + BW - 1 <= N - 2);

    float4 u[R];

    if (tile_interior) {
        #pragma unroll
        for (int r = 0; r < R; r++) {
            const float* p = in + (size_t)(gy0 + ybase + r) * N + gx0 + x4;
            u[r].x = p[0]; u[r].y = p[1]; u[r].z = p[2]; u[r].w = p[3];
        }
    } else {
        #pragma unroll
        for (int r = 0; r < R; r++) {
            int gy = gy0 + ybase + r;
            float4 v = make_float4(0.f, 0.f, 0.f, 0.f);
            if (gy >= 0 && gy < N) {
                const float* row = in + (size_t)gy * N;
                int g = gx0 + x4;
                if (g + 0 >= 0 && g + 0 < N) v.x = row[g + 0];
                if (g + 1 >= 0 && g + 1 < N) v.y = row[g + 1];
                if (g + 2 >= 0 && g + 2 < N) v.z = row[g + 2];
                if (g + 3 >= 0 && g + 3 < N) v.w = row[g + 3];
            }
            u[r] = v;
        }
    }

    if (tile_interior)
        run_steps<false>(u, ex, warp, x4, gx0, gy0, ybase);
    else
        run_steps<true>(u, ex, warp, x4, gx0, gy0, ybase);

    store_center(u, out, warp, lane, x4, gx0, gy0, ybase);
}

extern "C" void kernel_launch(void* const* d_in, const int* in_sizes, int n_in,
                              void* d_out, int out_size) {
    const float* X = (const float*)d_in[0];
    const float* Y = (const float*)d_in[1];
    float* A = (float*)d_out;
    float* B;
    cudaGetSymbolAddress((void**)&B, g_buf);

    dim3 grid(NBLK, NBLK);

    // pass 0 (fused init + 10 steps): (X,Y) -> B
    jacobi_first<<<grid, NTH>>>(X, Y, B);

    // passes 1..9: odd p: B -> A, even p: A -> B; p=9 ends in A (=d_out)
    for (int p = 1; p < 10; p++) {
        const float* src = (p & 1) ? B : A;
        float*       dst = (p & 1) ? A : B;
        jacobi_pass<<<grid, NTH>>>(src, dst);
    }
}